// round 3
// baseline (speedup 1.0000x reference)
#include <cuda_runtime.h>
#include <cuda_bf16.h>
#include <cstddef>

#define HW 16384
#define SCALE 0.17677669529663689f
#define EPSBN 1e-5f

// ---------------- scratch ----------------
__device__ float g_y1[2 * 256 * HW];
__device__ float g_q [2 * 256 * HW];
__device__ float g_kv[2 * 512 * HW];
__device__ float g_y2[2 * 256 * HW];

// ---------------- GEMM (Round-1 proven version): Out[o,p] = sum_c W[o,c]*X[c,p] ----------------
// MODE 0: plain   MODE 1: relu(bn(.))   MODE 2: relu(resid + gamma*relu(bn(.)))
template<int MODE>
__global__ __launch_bounds__(256) void gemm_conv(
    const float* __restrict__ X, const float* __restrict__ Wm, float* __restrict__ Out, int M,
    const float* __restrict__ bw, const float* __restrict__ bb,
    const float* __restrict__ bm, const float* __restrict__ bv,
    const float* __restrict__ gamma, const float* __restrict__ resid)
{
    __shared__ float Ws[16][68];
    __shared__ float Xs[16][128];
    const int tid = threadIdx.x;
    const int p0 = blockIdx.x * 128;
    const int o0 = blockIdx.y * 64;
    const int z  = blockIdx.z;
    const float* Xb = X + (size_t)z * 256 * HW;
    float* Ob = Out + (size_t)z * M * HW;
    const int tx = tid & 15, ty = tid >> 4;

    float acc[4][8];
#pragma unroll
    for (int ii = 0; ii < 4; ii++)
#pragma unroll
        for (int jj = 0; jj < 8; jj++) acc[ii][jj] = 0.f;

    const int wrow = tid >> 2;
    const int wc4  = (tid & 3) * 4;

    for (int k0 = 0; k0 < 256; k0 += 16) {
        float4 w4 = *(const float4*)&Wm[(o0 + wrow) * 256 + k0 + wc4];
        Ws[wc4 + 0][wrow] = w4.x;
        Ws[wc4 + 1][wrow] = w4.y;
        Ws[wc4 + 2][wrow] = w4.z;
        Ws[wc4 + 3][wrow] = w4.w;
#pragma unroll
        for (int it = 0; it < 2; it++) {
            int idx = tid + it * 256;
            int row = idx >> 5, cg = idx & 31;
            float4 xv = *(const float4*)&Xb[(size_t)(k0 + row) * HW + p0 + cg * 4];
            *(float4*)&Xs[row][cg * 4] = xv;
        }
        __syncthreads();
#pragma unroll
        for (int kk = 0; kk < 16; kk++) {
            float4 a4 = *(float4*)&Ws[kk][ty * 4];
            float4 b0 = *(float4*)&Xs[kk][tx * 8];
            float4 b1 = *(float4*)&Xs[kk][tx * 8 + 4];
            float a[4] = {a4.x, a4.y, a4.z, a4.w};
            float bvv[8] = {b0.x, b0.y, b0.z, b0.w, b1.x, b1.y, b1.z, b1.w};
#pragma unroll
            for (int ii = 0; ii < 4; ii++)
#pragma unroll
                for (int jj = 0; jj < 8; jj++)
                    acc[ii][jj] = fmaf(a[ii], bvv[jj], acc[ii][jj]);
        }
        __syncthreads();
    }

#pragma unroll
    for (int ii = 0; ii < 4; ii++) {
        int o = o0 + ty * 4 + ii;
        float mul = 1.f, add = 0.f, gm = 0.f;
        if (MODE >= 1) {
            float inv = bw[o] * rsqrtf(bv[o] + EPSBN);
            mul = inv;
            add = fmaf(-bm[o], inv, bb[o]);
        }
        if (MODE == 2) gm = gamma[o];
        float* orow = &Ob[(size_t)o * HW + p0 + tx * 8];
        const float* rrow = (MODE == 2) ? &resid[((size_t)z * 256 + o) * HW + p0 + tx * 8] : nullptr;
        float outv[8];
#pragma unroll
        for (int jj = 0; jj < 8; jj++) {
            float v = acc[ii][jj];
            if (MODE >= 1) { v = fmaf(v, mul, add); v = fmaxf(v, 0.f); }
            if (MODE == 2) { v = fmaf(gm, v, rrow[jj]); v = fmaxf(v, 0.f); }
            outv[jj] = v;
        }
        *(float4*)&orow[0] = make_float4(outv[0], outv[1], outv[2], outv[3]);
        *(float4*)&orow[4] = make_float4(outv[4], outv[5], outv[6], outv[7]);
    }
}

// ---------------- Halo attention: 3-phase exact softmax ----------------
// 256 threads/CTA, 2 CTAs/SM. Phase A: logits (thread = q-row x key-quarter, 49 keys).
// S[64][197] overlaps the K/Q/QH/QW smem region (dead after phase A).
// Phase B: exact softmax, 4 threads/row via shfl. Phase C: O = P @ V + fused relu(bna).
#define KS 36
#define SSTRIDE 197
// V 196*36 = 7056 ; union region: K 7056 + Q 64*36=2304 + QH 1728 + QW 1728 = 12816 >= S 64*197=12608
#define ATTN_SMEM_FLOATS (7056 + 12816)

__global__ __launch_bounds__(256, 2) void attn_kernel(
    const float* __restrict__ q, const float* __restrict__ kv,
    const float* __restrict__ hrel, const float* __restrict__ wrel,
    const float* __restrict__ aw, const float* __restrict__ ab,
    const float* __restrict__ am, const float* __restrict__ av,
    float* __restrict__ y2)
{
    extern __shared__ float sm[];
    float* Vsm = sm;                 // 196 * 36
    float* U   = sm + 7056;          // union region
    float* Ksm = U;                  // 196 * 36
    float* Qsm = U + 7056;           // 64 * 36
    float* QH  = U + 9360;           // 64 * 27
    float* QW  = U + 11088;          // 64 * 27
    float* S   = U;                  // 64 * 197 (overlaps K/Q/QH/QW)

    const int blk = blockIdx.x, bh = blockIdx.y;
    const int b = bh >> 3, head = bh & 7;
    const int hb = blk >> 4, wb = blk & 15;
    const int tid = threadIdx.x;

    // ---- load Q tile (64 q-positions x 32 dims, stride 36) ----
    const int qchan = b * 256 + head * 32;
    for (int idx = tid; idx < 2048; idx += 256) {
        int d = idx >> 6, qq = idx & 63;
        int ii = qq >> 3, jj = qq & 7;
        Qsm[qq * KS + d] =
            q[((size_t)(qchan + d) << 14) + (hb * 8 + ii) * 128 + wb * 8 + jj];
    }

    // ---- gather K/V halo window (196 x 32 each), zero-padded ----
    const int r0 = hb * 8 - 3, c0 = wb * 8 - 3;
    const int kvchan = b * 512 + head * 64;
    for (int e = tid; e < 196 * 64; e += 256) {
        int dd = e / 196, kp = e - dd * 196;
        int kh = kp / 14, kw = kp - kh * 14;
        int r = r0 + kh, c = c0 + kw;
        float val = 0.f;
        if ((unsigned)r < 128u && (unsigned)c < 128u)
            val = kv[((size_t)(kvchan + dd) << 14) + r * 128 + c];
        if (dd < 32) Ksm[kp * KS + dd] = val;
        else         Vsm[kp * KS + dd - 32] = val;
    }
    __syncthreads();

    // ---- relative-position dots: QH[t][r] = Q_t . hrel[r]; QW likewise ----
    for (int idx = tid; idx < 1728; idx += 256) {
        int row = idx / 27, r = idx - row * 27;
        float s1 = 0.f, s2 = 0.f;
        const float* qr = Qsm + row * KS;
        const float* hr = hrel + r * 32;
        const float* wr = wrel + r * 32;
#pragma unroll 8
        for (int d = 0; d < 32; d++) {
            s1 = fmaf(qr[d], hr[d], s1);
            s2 = fmaf(qr[d], wr[d], s2);
        }
        QH[idx] = s1; QW[idx] = s2;
    }
    __syncthreads();

    // ================= Phase A: logits into registers =================
    {
        const int row = tid & 63, qr = tid >> 6;   // warp-uniform qr -> K reads broadcast
        const int i = row >> 3, j = row & 7;
        float qreg[32];
#pragma unroll
        for (int u = 0; u < 32; u++) qreg[u] = Qsm[row * KS + u] * SCALE;
        const float* QHrow = QH + row * 27 + 13 - i;   // + kh
        const float* QWrow = QW + row * 27 + 13 - j;   // + kw

        float s[49];
#pragma unroll
        for (int kk = 0; kk < 49; kk++) {
            const int key = qr * 49 + kk;
            const int kh = key / 14, kw = key - kh * 14;
            const float4* K4 = (const float4*)(Ksm + key * KS);
            float d0 = 0.f, d1 = 0.f, d2 = 0.f, d3 = 0.f;
#pragma unroll
            for (int u = 0; u < 8; u++) {
                float4 k4 = K4[u];
                d0 = fmaf(qreg[u * 4 + 0], k4.x, d0);
                d1 = fmaf(qreg[u * 4 + 1], k4.y, d1);
                d2 = fmaf(qreg[u * 4 + 2], k4.z, d2);
                d3 = fmaf(qreg[u * 4 + 3], k4.w, d3);
            }
            s[kk] = (d0 + d1) + (d2 + d3) + QHrow[kh] + QWrow[kw];
        }
        __syncthreads();   // all reads of K/Q/QH/QW complete before S overwrite
        float* srow = S + row * SSTRIDE + qr * 49;
#pragma unroll
        for (int kk = 0; kk < 49; kk++) srow[kk] = s[kk];
    }
    __syncthreads();

    // ================= Phase B: exact softmax (4 threads per row) =================
    {
        const int row = tid >> 2, part = tid & 3;
        float* srow = S + row * SSTRIDE + part * 49;
        float e[49];
        float mx = -1e30f;
#pragma unroll
        for (int kk = 0; kk < 49; kk++) { e[kk] = srow[kk]; mx = fmaxf(mx, e[kk]); }
        mx = fmaxf(mx, __shfl_xor_sync(0xffffffffu, mx, 1));
        mx = fmaxf(mx, __shfl_xor_sync(0xffffffffu, mx, 2));
        float l = 0.f;
#pragma unroll
        for (int kk = 0; kk < 49; kk++) { e[kk] = __expf(e[kk] - mx); l += e[kk]; }
        l += __shfl_xor_sync(0xffffffffu, l, 1);
        l += __shfl_xor_sync(0xffffffffu, l, 2);
        const float invl = 1.f / l;
#pragma unroll
        for (int kk = 0; kk < 49; kk++) srow[kk] = e[kk] * invl;
    }
    __syncthreads();

    // ================= Phase C: O = P @ V, fused relu(bna) =================
    {
        const int row = tid >> 2, dg = (tid & 3) * 8;
        const int i = row >> 3, j = row & 7;
        const float* srow = S + row * SSTRIDE;
        float4 a0 = make_float4(0.f, 0.f, 0.f, 0.f);
        float4 a1 = make_float4(0.f, 0.f, 0.f, 0.f);
#pragma unroll 4
        for (int k = 0; k < 196; k++) {
            const float p = srow[k];
            const float4 v0 = *(const float4*)(Vsm + k * KS + dg);
            const float4 v1 = *(const float4*)(Vsm + k * KS + dg + 4);
            a0.x = fmaf(p, v0.x, a0.x); a0.y = fmaf(p, v0.y, a0.y);
            a0.z = fmaf(p, v0.z, a0.z); a0.w = fmaf(p, v0.w, a0.w);
            a1.x = fmaf(p, v1.x, a1.x); a1.y = fmaf(p, v1.y, a1.y);
            a1.z = fmaf(p, v1.z, a1.z); a1.w = fmaf(p, v1.w, a1.w);
        }
        const size_t obase = ((size_t)(b * 256 + head * 32 + dg) << 14)
                           + (hb * 8 + i) * 128 + wb * 8 + j;
        float vals[8] = {a0.x, a0.y, a0.z, a0.w, a1.x, a1.y, a1.z, a1.w};
#pragma unroll
        for (int cc = 0; cc < 8; cc++) {
            const int ch = head * 32 + dg + cc;
            const float inv  = aw[ch] * rsqrtf(av[ch] + EPSBN);
            const float bias = fmaf(-am[ch], inv, ab[ch]);
            float v = fmaf(vals[cc], inv, bias);
            v = fmaxf(v, 0.f);
            y2[obase + ((size_t)cc << 14)] = v;
        }
    }
}

// ---------------- launch ----------------
extern "C" void kernel_launch(void* const* d_in, const int* in_sizes, int n_in,
                              void* d_out, int out_size)
{
    const float* x     = (const float*)d_in[0];
    const float* w1    = (const float*)d_in[1];
    const float* qw    = (const float*)d_in[2];
    const float* kvw   = (const float*)d_in[3];
    const float* w3    = (const float*)d_in[4];
    const float* hrel  = (const float*)d_in[5];
    const float* wrel  = (const float*)d_in[6];
    const float* bn1w  = (const float*)d_in[7];
    const float* bn1b  = (const float*)d_in[8];
    const float* bn1m  = (const float*)d_in[9];
    const float* bn1v  = (const float*)d_in[10];
    const float* bnaw  = (const float*)d_in[11];
    const float* bnab  = (const float*)d_in[12];
    const float* bnam  = (const float*)d_in[13];
    const float* bnav  = (const float*)d_in[14];
    const float* bn3w  = (const float*)d_in[15];
    const float* bn3b  = (const float*)d_in[16];
    const float* bn3m  = (const float*)d_in[17];
    const float* bn3v  = (const float*)d_in[18];
    const float* gamma = (const float*)d_in[19];
    float* out = (float*)d_out;

    float *p_y1, *p_q, *p_kv, *p_y2;
    cudaGetSymbolAddress((void**)&p_y1, g_y1);
    cudaGetSymbolAddress((void**)&p_q,  g_q);
    cudaGetSymbolAddress((void**)&p_kv, g_kv);
    cudaGetSymbolAddress((void**)&p_y2, g_y2);

    const int attn_smem = ATTN_SMEM_FLOATS * 4;
    cudaFuncSetAttribute(attn_kernel, cudaFuncAttributeMaxDynamicSharedMemorySize, attn_smem);

    dim3 blk(256);
    // 1) y1 = relu(bn1(w1 @ x))
    gemm_conv<1><<<dim3(128, 4, 2), blk>>>(x, w1, p_y1, 256,
                                           bn1w, bn1b, bn1m, bn1v, nullptr, nullptr);
    // 2) q = q_w @ y1
    gemm_conv<0><<<dim3(128, 4, 2), blk>>>(p_y1, qw, p_q, 256,
                                           nullptr, nullptr, nullptr, nullptr, nullptr, nullptr);
    // 3) kv = kv_w @ y1
    gemm_conv<0><<<dim3(128, 8, 2), blk>>>(p_y1, kvw, p_kv, 512,
                                           nullptr, nullptr, nullptr, nullptr, nullptr, nullptr);
    // 4) attention + fused relu(bna(.))
    attn_kernel<<<dim3(256, 16), 256, attn_smem>>>(p_q, p_kv, hrel, wrel,
                                                   bnaw, bnab, bnam, bnav, p_y2);
    // 5) out = relu(x + gamma*relu(bn3(w3 @ y2)))
    gemm_conv<2><<<dim3(128, 4, 2), blk>>>(p_y2, w3, out, 256,
                                           bn3w, bn3b, bn3m, bn3v, gamma, x);
}